// round 7
// baseline (speedup 1.0000x reference)
#include <cuda_runtime.h>
#include <cuda_fp16.h>
#include <cstdint>
#include <math.h>

#define MAXN   4096
#define MAXD   512
#define NB     1024
#define MARGIN 0.3f
#define BIGD2  3.0e38f

// ---------------- scratch ----------------
__device__ __align__(16) int8_t g_q1[MAXN * MAXD];
__device__ __align__(16) int8_t g_q2[MAXN * MAXD];
__device__ float    g_sq[MAXN];
__device__ float    g_rowmax[MAXN];
__device__ float    g_maxabs;
__device__ float    g_hp2[MAXN];
__device__ float    g_hpB2[MAXN];
__device__ unsigned g_hnfb[MAXN];
__device__ unsigned g_hnsemi[MAXN];
__device__ int      g_semiflag;
__device__ int      g_ccount[NB];
__device__ int      g_coff[NB];
__device__ int      g_clist[MAXN];

__device__ __forceinline__ uint32_t smem_u32(const void* p) {
    uint32_t a;
    asm("{ .reg .u64 t; cvta.to.shared.u64 t, %1; cvt.u32.u64 %0, t; }" : "=r"(a) : "l"(p));
    return a;
}

#define CP_ASYNC16(dst, src) \
    asm volatile("cp.async.cg.shared.global [%0], [%1], 16;" :: "r"(dst), "l"(src))
#define CP_COMMIT() asm volatile("cp.async.commit_group;")
#define CP_WAIT1()  asm volatile("cp.async.wait_group 1;")
#define CP_WAIT0()  asm volatile("cp.async.wait_group 0;")

#define LDM4(r0, r1, r2, r3, addr)                                              \
    asm volatile("ldmatrix.sync.aligned.m8n8.x4.shared.b16 {%0,%1,%2,%3}, [%4];" \
        : "=r"(r0), "=r"(r1), "=r"(r2), "=r"(r3) : "r"(addr))

#define IMMA16832(c, a, b0, b1)                                                 \
    asm volatile("mma.sync.aligned.m16n8k32.row.col.s32.s8.s8.s32 "             \
        "{%0,%1,%2,%3},{%4,%5,%6,%7},{%8,%9},{%0,%1,%2,%3};"                    \
        : "+r"((c)[0]), "+r"((c)[1]), "+r"((c)[2]), "+r"((c)[3])                \
        : "r"((a)[0]), "r"((a)[1]), "r"((a)[2]), "r"((a)[3]), "r"(b0), "r"(b1))

// ---------------- kernel 0: row sq + row maxabs + per-row init ----------------
__global__ void convsq_kernel(const float* __restrict__ E, int d) {
    int row = blockIdx.x;
    int t = threadIdx.x;
    const float4* p = (const float4*)(E + (size_t)row * d);
    int d4 = d >> 2;
    float s = 0.f, m = 0.f;
    for (int c = t; c < d4; c += blockDim.x) {
        float4 v = p[c];
        s += v.x * v.x + v.y * v.y + v.z * v.z + v.w * v.w;
        m = fmaxf(m, fmaxf(fmaxf(fabsf(v.x), fabsf(v.y)), fmaxf(fabsf(v.z), fabsf(v.w))));
    }
    for (int o = 16; o; o >>= 1) {
        s += __shfl_xor_sync(0xffffffffu, s, o);
        m = fmaxf(m, __shfl_xor_sync(0xffffffffu, m, o));
    }
    __shared__ float ws[4], wm[4];
    int lane = t & 31, w = t >> 5;
    if (lane == 0) { ws[w] = s; wm[w] = m; }
    __syncthreads();
    if (t == 0) {
        float tot = 0.f, mx = 0.f;
        for (int k = 0; k < (int)(blockDim.x >> 5); k++) { tot += ws[k]; mx = fmaxf(mx, wm[k]); }
        g_sq[row] = tot;
        g_rowmax[row] = mx;
        g_hnfb[row] = 0u;
        g_hnsemi[row] = __float_as_uint(BIGD2);
        if (row == 0) g_semiflag = 0;
    }
}

// ---------------- kernel 1: hist + scan + fill + global maxabs (single block) --------
__global__ void classlist_kernel(const int* __restrict__ labels, int n) {
    __shared__ int cnt[NB];
    __shared__ int s[NB];
    __shared__ int cur[NB];
    __shared__ float mx[NB];
    int t = threadIdx.x;
    cnt[t] = 0;
    float m = 0.f;
    for (int i = t; i < n; i += blockDim.x) m = fmaxf(m, g_rowmax[i]);
    mx[t] = m;
    __syncthreads();
    for (int i = t; i < n; i += blockDim.x) atomicAdd(&cnt[labels[i] & (NB - 1)], 1);
    __syncthreads();
    int v = cnt[t];
    s[t] = v;
    for (int off = 1; off < NB; off <<= 1) {
        __syncthreads();
        int u = (t >= off) ? s[t - off] : 0;
        float fm = (t >= off) ? mx[t - off] : 0.f;
        __syncthreads();
        s[t] += u;
        mx[t] = fmaxf(mx[t], fm);
    }
    __syncthreads();
    int excl = s[t] - v;
    g_coff[t] = excl;
    g_ccount[t] = v;
    cur[t] = excl;
    if (t == NB - 1) g_maxabs = mx[t];
    __syncthreads();
    for (int i = t; i < n; i += blockDim.x) {
        int c = labels[i] & (NB - 1);
        int pos = atomicAdd(&cur[c], 1);
        g_clist[pos] = i;
    }
}

// ---------------- kernel 2: two-level int8 quantization ----------------
__global__ void quant_kernel(const float* __restrict__ E, int total) {
    float ma = g_maxabs;
    float s1 = ma * (1.f / 127.f);
    float inv1 = 1.f / s1;
    float s2 = s1 * (1.f / 252.f);
    float inv2 = 1.f / s2;
    int t4 = total >> 2;
    for (int i = blockIdx.x * blockDim.x + threadIdx.x; i < t4; i += gridDim.x * blockDim.x) {
        float4 v = ((const float4*)E)[i];
        char q1[4], q2[4];
        float xs[4] = {v.x, v.y, v.z, v.w};
#pragma unroll
        for (int j = 0; j < 4; j++) {
            float x = xs[j];
            float q1f = rintf(x * inv1);
            q1f = fminf(fmaxf(q1f, -127.f), 127.f);
            float r1 = fmaf(-s1, q1f, x);
            float q2f = rintf(r1 * inv2);
            q2f = fminf(fmaxf(q2f, -127.f), 127.f);
            q1[j] = (char)(int)q1f;
            q2[j] = (char)(int)q2f;
        }
        *(char4*)(g_q1 + 4 * (size_t)i) = make_char4(q1[0], q1[1], q1[2], q1[3]);
        *(char4*)(g_q2 + 4 * (size_t)i) = make_char4(q2[0], q2[1], q2[2], q2[3]);
    }
}

// ---------------- kernel 3: exact fp32 hardest positive (1 warp / anchor) ----------------
__global__ void hp_kernel(const float* __restrict__ E, const int* __restrict__ labels,
                          int n, int d) {
    int w = (blockIdx.x * blockDim.x + threadIdx.x) >> 5;
    int lid = threadIdx.x & 31;
    if (w >= n) return;
    int c = labels[w] & (NB - 1);
    const float4* ea = (const float4*)(E + (size_t)w * d);
    int dk4 = d >> 7;
    float4 a0[MAXD / 128];
#pragma unroll
    for (int j = 0; j < MAXD / 128; j++) if (j < dk4) a0[j] = ea[lid + 32 * j];
    int beg = g_coff[c], cnt = g_ccount[c];
    float sqa = g_sq[w];
    float maxd2 = 0.f;
    for (int t = 0; t < cnt; t++) {
        int m = g_clist[beg + t];
        const float4* em = (const float4*)(E + (size_t)m * d);
        float dot = 0.f;
#pragma unroll
        for (int j = 0; j < MAXD / 128; j++)
            if (j < dk4) {
                float4 b = em[lid + 32 * j];
                dot += a0[j].x * b.x + a0[j].y * b.y + a0[j].z * b.z + a0[j].w * b.w;
            }
        for (int o = 16; o; o >>= 1) dot += __shfl_xor_sync(0xffffffffu, dot, o);
        float d2 = sqa + g_sq[m] - 2.f * dot;
        maxd2 = fmaxf(maxd2, d2);
    }
    if (lid == 0) {
        float h2 = fmaxf(maxd2, 1e-12f);
        g_hp2[w] = h2;
        float hp = sqrtf(h2);
        g_hpB2[w] = (hp + MARGIN) * (hp + MARGIN);
    }
}

// ---------------- kernel 4: IMMA s8 GEMM, triangle tiles, fused 2-sided epilogue ------
#define BKQ     64                    // s8 elems per k-chunk = 64 B rows
#define TILEQ   8192                  // 128 rows * 64 B
#define STAGEQ  (4 * TILEQ)           // Aq1, Aq2, Bq1, Bq2 = 32 KB
#define AUXO    (3 * STAGEQ)          // 98304
#define SMEM_DYN (AUXO + 6144)

__global__ __launch_bounds__(512, 1) void gemm_kernel(const int* __restrict__ labels,
                                                      int n, int d) {
    extern __shared__ char sm[];
    uint32_t sb = smem_u32(sm);
    int tid = threadIdx.x, lane = tid & 31, wid = tid >> 5;
    int wm = wid >> 2, wn = wid & 3;   // 4x4 warp grid; warp tile 32x32

    int bid = blockIdx.x;
    int by = (int)((sqrtf(8.f * (float)bid + 1.f) - 1.f) * 0.5f);
    while ((by + 1) * (by + 2) / 2 <= bid) by++;
    while (by * (by + 1) / 2 > bid) by--;
    int bx = bid - by * (by + 1) / 2;
    int rowBase = by * 128, colBase = bx * 128;

    float*    s_sqc  = (float*)(sm + AUXO);
    int*      s_labc = (int*)(sm + AUXO + 512);
    float*    s_sqr  = (float*)(sm + AUXO + 1024);
    int*      s_labr = (int*)(sm + AUXO + 1536);
    float*    s_hp2r = (float*)(sm + AUXO + 2048);
    float*    s_hpBr = (float*)(sm + AUXO + 2560);
    float*    s_hp2c = (float*)(sm + AUXO + 3072);
    float*    s_hpBc = (float*)(sm + AUXO + 3584);
    unsigned* shRmax = (unsigned*)(sm + AUXO + 4096);
    unsigned* shRmin = (unsigned*)(sm + AUXO + 4608);
    unsigned* shCmax = (unsigned*)(sm + AUXO + 5120);
    unsigned* shCmin = (unsigned*)(sm + AUXO + 5632);

    if (tid < 128) {
        s_sqc[tid]  = g_sq[colBase + tid];  s_labc[tid] = labels[colBase + tid];
        s_sqr[tid]  = g_sq[rowBase + tid];  s_labr[tid] = labels[rowBase + tid];
        s_hp2r[tid] = g_hp2[rowBase + tid]; s_hpBr[tid] = g_hpB2[rowBase + tid];
        s_hp2c[tid] = g_hp2[colBase + tid]; s_hpBc[tid] = g_hpB2[colBase + tid];
        shRmax[tid] = 0u; shRmin[tid] = __float_as_uint(BIGD2);
        shCmax[tid] = 0u; shCmin[tid] = __float_as_uint(BIGD2);
    }

    // cp.async: 4 tiles x 512 chunks(16B) per stage / 512 threads = 4 per thread
    const int8_t* gsrc[4];
    uint32_t sdst[4];
    {
        const int8_t* tps[4] = {g_q1 + (size_t)rowBase * d, g_q2 + (size_t)rowBase * d,
                                g_q1 + (size_t)colBase * d, g_q2 + (size_t)colBase * d};
        int r = tid >> 2, ch = tid & 3;
#pragma unroll
        for (int t = 0; t < 4; t++) {
            gsrc[t] = tps[t] + (size_t)r * d + ch * 16;
            sdst[t] = sb + t * TILEQ + r * 64 + (((ch + (r >> 1)) & 3) << 4);
        }
    }

    // per-lane swizzled ldmatrix addresses (step stride = 32 B = 2 chunks)
    int r0A = wm * 32 + (lane & 15);
    int cA  = lane >> 4;
    uint32_t aoff0 = (uint32_t)(r0A * 64 + (((cA + (r0A >> 1)) & 3) << 4));
    uint32_t aoff1 = (uint32_t)(r0A * 64 + (((cA + 2 + (r0A >> 1)) & 3) << 4));
    int r0B = wn * 32 + (lane & 7) + ((lane >> 4) & 1) * 8;
    int cB  = (lane >> 3) & 1;
    uint32_t boff0 = (uint32_t)(r0B * 64 + (((cB + (r0B >> 1)) & 3) << 4));
    uint32_t boff1 = (uint32_t)(r0B * 64 + (((cB + 2 + (r0B >> 1)) & 3) << 4));

    int c11[2][4][4], c12[2][4][4];
#pragma unroll
    for (int im = 0; im < 2; im++)
#pragma unroll
        for (int in = 0; in < 4; in++)
#pragma unroll
            for (int e = 0; e < 4; e++) { c11[im][in][e] = 0; c12[im][in][e] = 0; }

    int NC = d / BKQ;   // 8

    // prologue: stages 0 and 1
#pragma unroll
    for (int t = 0; t < 4; t++) CP_ASYNC16(sdst[t], gsrc[t]);
    CP_COMMIT();
#pragma unroll
    for (int t = 0; t < 4; t++) CP_ASYNC16(sdst[t] + STAGEQ, gsrc[t] + BKQ);
    CP_COMMIT();

    int cb = 0, ib = 2;
    for (int c = 0; c < NC; c++) {
        if (c + 1 < NC) { CP_WAIT1(); } else { CP_WAIT0(); }
        __syncthreads();
        if (c + 2 < NC) {
            int k0 = (c + 2) * BKQ;
            uint32_t so = (uint32_t)ib * STAGEQ;
#pragma unroll
            for (int t = 0; t < 4; t++) CP_ASYNC16(sdst[t] + so, gsrc[t] + k0);
            CP_COMMIT();
            ib = (ib == 2) ? 0 : ib + 1;
        }

        uint32_t base = sb + (uint32_t)cb * STAGEQ;
#pragma unroll
        for (int step = 0; step < 2; step++) {
            uint32_t ao = step ? aoff1 : aoff0;
            uint32_t bo = step ? boff1 : boff0;
            uint32_t aq1[2][4], aq2[2][4], bq1[4][2], bq2[4][2];
#pragma unroll
            for (int im = 0; im < 2; im++) {
                uint32_t aA = base + im * 1024 + ao;
                LDM4(aq1[im][0], aq1[im][1], aq1[im][2], aq1[im][3], aA);
                LDM4(aq2[im][0], aq2[im][1], aq2[im][2], aq2[im][3], aA + TILEQ);
            }
#pragma unroll
            for (int p = 0; p < 2; p++) {
                uint32_t aB = base + 2 * TILEQ + p * 1024 + bo;
                LDM4(bq1[2 * p][0], bq1[2 * p][1], bq1[2 * p + 1][0], bq1[2 * p + 1][1], aB);
                LDM4(bq2[2 * p][0], bq2[2 * p][1], bq2[2 * p + 1][0], bq2[2 * p + 1][1], aB + TILEQ);
            }
            // group 1: q1·q1 -> c11
#pragma unroll
            for (int im = 0; im < 2; im++)
#pragma unroll
                for (int in = 0; in < 4; in++)
                    IMMA16832(c11[im][in], aq1[im], bq1[in][0], bq1[in][1]);
            // group 2: q1·q2 -> c12
#pragma unroll
            for (int im = 0; im < 2; im++)
#pragma unroll
                for (int in = 0; in < 4; in++)
                    IMMA16832(c12[im][in], aq1[im], bq2[in][0], bq2[in][1]);
            // group 3: q2·q1 -> c12
#pragma unroll
            for (int im = 0; im < 2; im++)
#pragma unroll
                for (int in = 0; in < 4; in++)
                    IMMA16832(c12[im][in], aq2[im], bq1[in][0], bq1[in][1]);
        }
        cb = (cb == 2) ? 0 : cb + 1;
    }

    float s1f = g_maxabs * (1.f / 127.f);
    float s2f = s1f * (1.f / 252.f);
    float S11 = s1f * s1f, S12 = s1f * s2f;

    // ---- epilogue: row-side ----
#pragma unroll
    for (int im = 0; im < 2; im++)
#pragma unroll
        for (int eh = 0; eh < 2; eh++) {
            int rloc = wm * 32 + im * 16 + (lane >> 2) + eh * 8;
            float sqr = s_sqr[rloc];
            int   labr = s_labr[rloc];
            float A = s_hp2r[rloc], B = s_hpBr[rloc];
            float mx = 0.f, mn = BIGD2;
#pragma unroll
            for (int in = 0; in < 4; in++)
#pragma unroll
                for (int ec = 0; ec < 2; ec++) {
                    int cloc = wn * 32 + in * 8 + (lane & 3) * 2 + ec;
                    float dot = S11 * (float)c11[im][in][eh * 2 + ec]
                              + S12 * (float)c12[im][in][eh * 2 + ec];
                    float d2 = fmaxf(sqr + s_sqc[cloc] - 2.f * dot, 1e-12f);
                    if (labr != s_labc[cloc]) {
                        mx = fmaxf(mx, d2);
                        if (d2 > A && d2 < B) mn = fminf(mn, d2);
                    }
                }
            if (mx > 0.f) atomicMax(&shRmax[rloc], __float_as_uint(mx));
            if (mn < BIGD2) atomicMin(&shRmin[rloc], __float_as_uint(mn));
        }

    // ---- epilogue: col-side (symmetric) ----
#pragma unroll
    for (int in = 0; in < 4; in++)
#pragma unroll
        for (int ec = 0; ec < 2; ec++) {
            int cloc = wn * 32 + in * 8 + (lane & 3) * 2 + ec;
            float sqc = s_sqc[cloc];
            int   labc = s_labc[cloc];
            float A = s_hp2c[cloc], B = s_hpBc[cloc];
            float mx = 0.f, mn = BIGD2;
#pragma unroll
            for (int im = 0; im < 2; im++)
#pragma unroll
                for (int eh = 0; eh < 2; eh++) {
                    int rloc = wm * 32 + im * 16 + (lane >> 2) + eh * 8;
                    float dot = S11 * (float)c11[im][in][eh * 2 + ec]
                              + S12 * (float)c12[im][in][eh * 2 + ec];
                    float d2 = fmaxf(s_sqr[rloc] + sqc - 2.f * dot, 1e-12f);
                    if (labc != s_labr[rloc]) {
                        mx = fmaxf(mx, d2);
                        if (d2 > A && d2 < B) mn = fminf(mn, d2);
                    }
                }
            if (mx > 0.f) atomicMax(&shCmax[cloc], __float_as_uint(mx));
            if (mn < BIGD2) atomicMin(&shCmin[cloc], __float_as_uint(mn));
        }

    __syncthreads();
    if (tid < 128) {
        if (shRmax[tid]) atomicMax(&g_hnfb[rowBase + tid], shRmax[tid]);
        if (shRmin[tid] != __float_as_uint(BIGD2)) {
            atomicMin(&g_hnsemi[rowBase + tid], shRmin[tid]);
            g_semiflag = 1;
        }
        if (shCmax[tid]) atomicMax(&g_hnfb[colBase + tid], shCmax[tid]);
        if (shCmin[tid] != __float_as_uint(BIGD2)) {
            atomicMin(&g_hnsemi[colBase + tid], shCmin[tid]);
            g_semiflag = 1;
        }
    }
}

// ---------------- kernel 5: finalize ----------------
__global__ void finalize_kernel(float* __restrict__ out, int n) {
    bool useSemi = (g_semiflag != 0);
    float sum = 0.f;
    int cnt = 0;
    for (int i = threadIdx.x; i < n; i += blockDim.x) {
        float hp = sqrtf(g_hp2[i]);
        unsigned hb = useSemi ? g_hnsemi[i] : g_hnfb[i];
        float hn = sqrtf(__uint_as_float(hb));
        float t = hp - hn + MARGIN;
        if (t < 0.f) t = 0.f;
        sum += t;
        if (t > 0.f) cnt++;
    }
    for (int o = 16; o; o >>= 1) {
        sum += __shfl_xor_sync(0xffffffffu, sum, o);
        cnt += __shfl_xor_sync(0xffffffffu, cnt, o);
    }
    __shared__ float wsum[32];
    __shared__ int wcnt[32];
    int lane = threadIdx.x & 31, w = threadIdx.x >> 5;
    if (lane == 0) { wsum[w] = sum; wcnt[w] = cnt; }
    __syncthreads();
    if (threadIdx.x == 0) {
        float s = 0.f; int c = 0;
        for (int k = 0; k < (int)(blockDim.x >> 5); k++) { s += wsum[k]; c += wcnt[k]; }
        out[0] = (c > 0) ? (s / (float)c) : 0.0f;
    }
}

// ---------------- launch ----------------
extern "C" void kernel_launch(void* const* d_in, const int* in_sizes, int n_in,
                              void* d_out, int out_size) {
    const float* E = (const float*)d_in[0];
    const int* labels = (const int*)d_in[1];
    int n = in_sizes[1];
    int d = in_sizes[0] / n;

    cudaFuncSetAttribute(gemm_kernel, cudaFuncAttributeMaxDynamicSharedMemorySize, SMEM_DYN);

    convsq_kernel<<<n, 128>>>(E, d);
    classlist_kernel<<<1, NB>>>(labels, n);
    quant_kernel<<<256, 256>>>(E, n * d);
    hp_kernel<<<n / 4, 128>>>(E, labels, n, d);
    int nb = n / 128;
    gemm_kernel<<<nb * (nb + 1) / 2, 512, SMEM_DYN>>>(labels, n, d);
    finalize_kernel<<<1, 1024>>>((float*)d_out, n);
}

// round 8
// speedup vs baseline: 3.3022x; 3.3022x over previous
#include <cuda_runtime.h>
#include <cuda_fp16.h>
#include <cstdint>
#include <math.h>

#define MAXN   4096
#define MAXD   512
#define NB     1024
#define MARGIN 0.3f
#define BIGD2  3.0e38f

// ---------------- scratch ----------------
__device__ __align__(16) __half g_Ehi[MAXN * MAXD];
__device__ float    g_sq[MAXN];
__device__ float    g_hp2[MAXN];
__device__ float    g_hpB2[MAXN];
__device__ unsigned g_hnfb[MAXN];
__device__ unsigned g_hnsemi[MAXN];
__device__ int      g_semiflag;
__device__ int      g_ccount[NB];
__device__ int      g_coff[NB];
__device__ int      g_clist[MAXN];

__device__ __forceinline__ uint32_t smem_u32(const void* p) {
    uint32_t a;
    asm("{ .reg .u64 t; cvta.to.shared.u64 t, %1; cvt.u32.u64 %0, t; }" : "=r"(a) : "l"(p));
    return a;
}

#define CP_ASYNC16(dst, src) \
    asm volatile("cp.async.cg.shared.global [%0], [%1], 16;" :: "r"(dst), "l"(src))
#define CP_COMMIT() asm volatile("cp.async.commit_group;")
#define CP_WAIT1()  asm volatile("cp.async.wait_group 1;")
#define CP_WAIT0()  asm volatile("cp.async.wait_group 0;")

#define LDM4(r0, r1, r2, r3, addr)                                              \
    asm volatile("ldmatrix.sync.aligned.m8n8.x4.shared.b16 {%0,%1,%2,%3}, [%4];" \
        : "=r"(r0), "=r"(r1), "=r"(r2), "=r"(r3) : "r"(addr))

#define MMA16816(c, a, b0, b1)                                                   \
    asm volatile("mma.sync.aligned.m16n8k16.row.col.f32.f16.f16.f32 "            \
        "{%0,%1,%2,%3},{%4,%5,%6,%7},{%8,%9},{%0,%1,%2,%3};"                     \
        : "+f"((c)[0]), "+f"((c)[1]), "+f"((c)[2]), "+f"((c)[3])                 \
        : "r"((a)[0]), "r"((a)[1]), "r"((a)[2]), "r"((a)[3]), "r"(b0), "r"(b1))

// ---------------- kernel 0: convert(hi only) + row sq + per-row init ----------------
__global__ void convsq_kernel(const float* __restrict__ E, int d) {
    int row = blockIdx.x;
    int t = threadIdx.x;
    const float4* p = (const float4*)(E + (size_t)row * d);
    int d4 = d >> 2;
    float s = 0.f;
    for (int c = t; c < d4; c += blockDim.x) {
        float4 v = p[c];
        s += v.x * v.x + v.y * v.y + v.z * v.z + v.w * v.w;
        __half2 h01 = __halves2half2(__float2half(v.x), __float2half(v.y));
        __half2 h23 = __halves2half2(__float2half(v.z), __float2half(v.w));
        size_t o = (size_t)row * d + 4 * c;
        *(__half2*)(g_Ehi + o) = h01;
        *(__half2*)(g_Ehi + o + 2) = h23;
    }
    for (int o = 16; o; o >>= 1) s += __shfl_xor_sync(0xffffffffu, s, o);
    __shared__ float ws[4];
    int lane = t & 31, w = t >> 5;
    if (lane == 0) ws[w] = s;
    __syncthreads();
    if (t == 0) {
        float tot = 0.f;
        for (int k = 0; k < (int)(blockDim.x >> 5); k++) tot += ws[k];
        g_sq[row] = tot;
        g_hnfb[row] = 0u;
        g_hnsemi[row] = __float_as_uint(BIGD2);
        if (row == 0) g_semiflag = 0;
    }
}

// ---------------- kernel 1: hist + scan + fill (single block) ----------------
__global__ void classlist_kernel(const int* __restrict__ labels, int n) {
    __shared__ int cnt[NB];
    __shared__ int s[NB];
    __shared__ int cur[NB];
    int t = threadIdx.x;
    cnt[t] = 0;
    __syncthreads();
    for (int i = t; i < n; i += blockDim.x) atomicAdd(&cnt[labels[i] & (NB - 1)], 1);
    __syncthreads();
    int v = cnt[t];
    s[t] = v;
    for (int off = 1; off < NB; off <<= 1) {
        __syncthreads();
        int u = (t >= off) ? s[t - off] : 0;
        __syncthreads();
        s[t] += u;
    }
    __syncthreads();
    int excl = s[t] - v;
    g_coff[t] = excl;
    g_ccount[t] = v;
    cur[t] = excl;
    __syncthreads();
    for (int i = t; i < n; i += blockDim.x) {
        int c = labels[i] & (NB - 1);
        int pos = atomicAdd(&cur[c], 1);
        g_clist[pos] = i;
    }
}

// ---------------- kernel 2: exact fp32 hardest positive (block per anchor, 4 warps) --
__global__ void hp_kernel(const float* __restrict__ E, const int* __restrict__ labels,
                          int n, int d) {
    int anchor = blockIdx.x;
    int lid = threadIdx.x & 31, wid = threadIdx.x >> 5;
    int c = labels[anchor] & (NB - 1);
    const float4* ea = (const float4*)(E + (size_t)anchor * d);
    int dk4 = d >> 7;                       // 4 for d=512
    float4 a0[MAXD / 128];
#pragma unroll
    for (int j = 0; j < MAXD / 128; j++) if (j < dk4) a0[j] = ea[lid + 32 * j];
    int beg = g_coff[c], cnt = g_ccount[c];
    float sqa = g_sq[anchor];
    float maxd2 = 0.f;
    for (int t = wid; t < cnt; t += 4) {
        int m = g_clist[beg + t];
        const float4* em = (const float4*)(E + (size_t)m * d);
        float dot = 0.f;
#pragma unroll
        for (int j = 0; j < MAXD / 128; j++)
            if (j < dk4) {
                float4 b = em[lid + 32 * j];
                dot += a0[j].x * b.x + a0[j].y * b.y + a0[j].z * b.z + a0[j].w * b.w;
            }
        for (int o = 16; o; o >>= 1) dot += __shfl_xor_sync(0xffffffffu, dot, o);
        float d2 = sqa + g_sq[m] - 2.f * dot;
        maxd2 = fmaxf(maxd2, d2);
    }
    __shared__ float wmax[4];
    if (lid == 0) wmax[wid] = maxd2;
    __syncthreads();
    if (threadIdx.x == 0) {
        float h2 = fmaxf(fmaxf(fmaxf(wmax[0], wmax[1]), fmaxf(wmax[2], wmax[3])), 1e-12f);
        g_hp2[anchor] = h2;
        float hp = sqrtf(h2);
        g_hpB2[anchor] = (hp + MARGIN) * (hp + MARGIN);
    }
}

// ---------------- kernel 3: HMMA GEMM (single product), 512 thr, 3-stage -------------
#define BK      32                    // halves per k-chunk (64 bytes)
#define TILEB   8192                  // 128 rows * 64 B
#define STAGEB  (2 * TILEB)           // Ahi, Bhi = 16 KB
#define AUXO    (3 * STAGEB)          // 49152
#define SMEM_DYN (AUXO + 6144)

__global__ __launch_bounds__(512, 1) void gemm_kernel(const int* __restrict__ labels,
                                                      int n, int d) {
    extern __shared__ char sm[];
    uint32_t sb = smem_u32(sm);
    int tid = threadIdx.x, lane = tid & 31, wid = tid >> 5;
    int wm = wid >> 2, wn = wid & 3;   // 4x4 warp grid; warp tile 32x32

    // triangle mapping: bid -> (by, bx), bx <= by
    int bid = blockIdx.x;
    int by = (int)((sqrtf(8.f * (float)bid + 1.f) - 1.f) * 0.5f);
    while ((by + 1) * (by + 2) / 2 <= bid) by++;
    while (by * (by + 1) / 2 > bid) by--;
    int bx = bid - by * (by + 1) / 2;
    int rowBase = by * 128, colBase = bx * 128;

    float*    s_sqc  = (float*)(sm + AUXO);
    int*      s_labc = (int*)(sm + AUXO + 512);
    float*    s_sqr  = (float*)(sm + AUXO + 1024);
    int*      s_labr = (int*)(sm + AUXO + 1536);
    float*    s_hp2r = (float*)(sm + AUXO + 2048);
    float*    s_hpBr = (float*)(sm + AUXO + 2560);
    float*    s_hp2c = (float*)(sm + AUXO + 3072);
    float*    s_hpBc = (float*)(sm + AUXO + 3584);
    unsigned* shRmax = (unsigned*)(sm + AUXO + 4096);
    unsigned* shRmin = (unsigned*)(sm + AUXO + 4608);
    unsigned* shCmax = (unsigned*)(sm + AUXO + 5120);
    unsigned* shCmin = (unsigned*)(sm + AUXO + 5632);

    if (tid < 128) {
        s_sqc[tid]  = g_sq[colBase + tid];  s_labc[tid] = labels[colBase + tid];
        s_sqr[tid]  = g_sq[rowBase + tid];  s_labr[tid] = labels[rowBase + tid];
        s_hp2r[tid] = g_hp2[rowBase + tid]; s_hpBr[tid] = g_hpB2[rowBase + tid];
        s_hp2c[tid] = g_hp2[colBase + tid]; s_hpBc[tid] = g_hpB2[colBase + tid];
        shRmax[tid] = 0u; shRmin[tid] = __float_as_uint(BIGD2);
        shCmax[tid] = 0u; shCmin[tid] = __float_as_uint(BIGD2);
    }

    // cp.async: 2 tiles x 512 chunks(16B) per stage / 512 threads = 2 per thread
    const __half* gsrc[2];
    uint32_t sdst[2];
    {
        const __half* tps[2] = {g_Ehi + (size_t)rowBase * d,
                                g_Ehi + (size_t)colBase * d};
        int r = tid >> 2, ch = tid & 3;
#pragma unroll
        for (int t = 0; t < 2; t++) {
            gsrc[t] = tps[t] + (size_t)r * d + ch * 8;
            sdst[t] = sb + t * TILEB + r * 64 + (((ch + (r >> 1)) & 3) << 4);
        }
    }

    // per-lane swizzled ldmatrix addresses
    int r0A = wm * 32 + (lane & 15);
    int cA  = lane >> 4;
    uint32_t aoff0 = (uint32_t)(r0A * 64 + (((cA + (r0A >> 1)) & 3) << 4));
    uint32_t aoff1 = (uint32_t)(r0A * 64 + (((cA + 2 + (r0A >> 1)) & 3) << 4));
    int r0B = wn * 32 + (lane & 7) + ((lane >> 4) & 1) * 8;
    int cB  = (lane >> 3) & 1;
    uint32_t boff0 = (uint32_t)(r0B * 64 + (((cB + (r0B >> 1)) & 3) << 4));
    uint32_t boff1 = (uint32_t)(r0B * 64 + (((cB + 2 + (r0B >> 1)) & 3) << 4));

    float acc[2][4][4];
#pragma unroll
    for (int im = 0; im < 2; im++)
#pragma unroll
        for (int in = 0; in < 4; in++)
#pragma unroll
            for (int e = 0; e < 4; e++) acc[im][in][e] = 0.f;

    int NC = d / BK;   // 16

    // prologue: stages 0 and 1
#pragma unroll
    for (int t = 0; t < 2; t++) CP_ASYNC16(sdst[t], gsrc[t]);
    CP_COMMIT();
#pragma unroll
    for (int t = 0; t < 2; t++) CP_ASYNC16(sdst[t] + STAGEB, gsrc[t] + BK);
    CP_COMMIT();

    int cb = 0, ib = 2;
    for (int c = 0; c < NC; c++) {
        if (c + 1 < NC) { CP_WAIT1(); } else { CP_WAIT0(); }
        __syncthreads();                           // stage cb visible; stage ib free
        if (c + 2 < NC) {
            int k0 = (c + 2) * BK;
            uint32_t so = (uint32_t)ib * STAGEB;
#pragma unroll
            for (int t = 0; t < 2; t++) CP_ASYNC16(sdst[t] + so, gsrc[t] + k0);
            CP_COMMIT();
            ib = (ib == 2) ? 0 : ib + 1;
        }

        uint32_t base = sb + (uint32_t)cb * STAGEB;
        uint32_t ah[2][2][4], bh[2][4][2];
#pragma unroll
        for (int k16 = 0; k16 < 2; k16++) {
            uint32_t ao = k16 ? aoff1 : aoff0;
            uint32_t bo = k16 ? boff1 : boff0;
#pragma unroll
            for (int im = 0; im < 2; im++) {
                uint32_t aA = base + im * 1024 + ao;
                LDM4(ah[k16][im][0], ah[k16][im][1], ah[k16][im][2], ah[k16][im][3], aA);
            }
#pragma unroll
            for (int p = 0; p < 2; p++) {
                uint32_t aB = base + TILEB + p * 1024 + bo;
                LDM4(bh[k16][2 * p][0], bh[k16][2 * p][1],
                     bh[k16][2 * p + 1][0], bh[k16][2 * p + 1][1], aB);
            }
        }
#pragma unroll
        for (int k16 = 0; k16 < 2; k16++)
#pragma unroll
            for (int im = 0; im < 2; im++)
#pragma unroll
                for (int in = 0; in < 4; in++)
                    MMA16816(acc[im][in], ah[k16][im], bh[k16][in][0], bh[k16][in][1]);
        cb = (cb == 2) ? 0 : cb + 1;
    }

    // ---- epilogue: row-side ----
#pragma unroll
    for (int im = 0; im < 2; im++)
#pragma unroll
        for (int eh = 0; eh < 2; eh++) {
            int rloc = wm * 32 + im * 16 + (lane >> 2) + eh * 8;
            float sqr = s_sqr[rloc];
            int   labr = s_labr[rloc];
            float A = s_hp2r[rloc], B = s_hpBr[rloc];
            float mx = 0.f, mn = BIGD2;
#pragma unroll
            for (int in = 0; in < 4; in++)
#pragma unroll
                for (int ec = 0; ec < 2; ec++) {
                    int cloc = wn * 32 + in * 8 + (lane & 3) * 2 + ec;
                    float dot = acc[im][in][eh * 2 + ec];
                    float d2 = fmaxf(sqr + s_sqc[cloc] - 2.f * dot, 1e-12f);
                    if (labr != s_labc[cloc]) {
                        mx = fmaxf(mx, d2);
                        if (d2 > A && d2 < B) mn = fminf(mn, d2);
                    }
                }
            if (mx > 0.f) atomicMax(&shRmax[rloc], __float_as_uint(mx));
            if (mn < BIGD2) atomicMin(&shRmin[rloc], __float_as_uint(mn));
        }

    // ---- epilogue: col-side (symmetric) ----
#pragma unroll
    for (int in = 0; in < 4; in++)
#pragma unroll
        for (int ec = 0; ec < 2; ec++) {
            int cloc = wn * 32 + in * 8 + (lane & 3) * 2 + ec;
            float sqc = s_sqc[cloc];
            int   labc = s_labc[cloc];
            float A = s_hp2c[cloc], B = s_hpBc[cloc];
            float mx = 0.f, mn = BIGD2;
#pragma unroll
            for (int im = 0; im < 2; im++)
#pragma unroll
                for (int eh = 0; eh < 2; eh++) {
                    int rloc = wm * 32 + im * 16 + (lane >> 2) + eh * 8;
                    float dot = acc[im][in][eh * 2 + ec];
                    float d2 = fmaxf(s_sqr[rloc] + sqc - 2.f * dot, 1e-12f);
                    if (labc != s_labr[rloc]) {
                        mx = fmaxf(mx, d2);
                        if (d2 > A && d2 < B) mn = fminf(mn, d2);
                    }
                }
            if (mx > 0.f) atomicMax(&shCmax[cloc], __float_as_uint(mx));
            if (mn < BIGD2) atomicMin(&shCmin[cloc], __float_as_uint(mn));
        }

    __syncthreads();
    if (tid < 128) {
        if (shRmax[tid]) atomicMax(&g_hnfb[rowBase + tid], shRmax[tid]);
        if (shRmin[tid] != __float_as_uint(BIGD2)) {
            atomicMin(&g_hnsemi[rowBase + tid], shRmin[tid]);
            g_semiflag = 1;
        }
        if (shCmax[tid]) atomicMax(&g_hnfb[colBase + tid], shCmax[tid]);
        if (shCmin[tid] != __float_as_uint(BIGD2)) {
            atomicMin(&g_hnsemi[colBase + tid], shCmin[tid]);
            g_semiflag = 1;
        }
    }
}

// ---------------- kernel 4: finalize ----------------
__global__ void finalize_kernel(float* __restrict__ out, int n) {
    bool useSemi = (g_semiflag != 0);
    float sum = 0.f;
    int cnt = 0;
    for (int i = threadIdx.x; i < n; i += blockDim.x) {
        float hp = sqrtf(g_hp2[i]);
        unsigned hb = useSemi ? g_hnsemi[i] : g_hnfb[i];
        float hn = sqrtf(__uint_as_float(hb));
        float t = hp - hn + MARGIN;
        if (t < 0.f) t = 0.f;
        sum += t;
        if (t > 0.f) cnt++;
    }
    for (int o = 16; o; o >>= 1) {
        sum += __shfl_xor_sync(0xffffffffu, sum, o);
        cnt += __shfl_xor_sync(0xffffffffu, cnt, o);
    }
    __shared__ float wsum[32];
    __shared__ int wcnt[32];
    int lane = threadIdx.x & 31, w = threadIdx.x >> 5;
    if (lane == 0) { wsum[w] = sum; wcnt[w] = cnt; }
    __syncthreads();
    if (threadIdx.x == 0) {
        float s = 0.f; int c = 0;
        for (int k = 0; k < (int)(blockDim.x >> 5); k++) { s += wsum[k]; c += wcnt[k]; }
        out[0] = (c > 0) ? (s / (float)c) : 0.0f;
    }
}

// ---------------- launch ----------------
extern "C" void kernel_launch(void* const* d_in, const int* in_sizes, int n_in,
                              void* d_out, int out_size) {
    const float* E = (const float*)d_in[0];
    const int* labels = (const int*)d_in[1];
    int n = in_sizes[1];
    int d = in_sizes[0] / n;

    cudaFuncSetAttribute(gemm_kernel, cudaFuncAttributeMaxDynamicSharedMemorySize, SMEM_DYN);

    convsq_kernel<<<n, 128>>>(E, d);                       // launch 0
    classlist_kernel<<<1, NB>>>(labels, n);                // launch 1
    hp_kernel<<<n, 128>>>(E, labels, n, d);                // launch 2
    int nb = n / 128;
    gemm_kernel<<<nb * (nb + 1) / 2, 512, SMEM_DYN>>>(labels, n, d);  // launch 3 (profiled)
    finalize_kernel<<<1, 1024>>>((float*)d_out, n);        // launch 4
}

// round 9
// speedup vs baseline: 3.6247x; 1.0977x over previous
#include <cuda_runtime.h>
#include <cuda_fp16.h>
#include <cstdint>
#include <math.h>

#define MAXN   4096
#define MAXD   512
#define NB     1024
#define MARGIN 0.3f
#define BIGD2  3.0e38f

// ---------------- scratch ----------------
__device__ __align__(16) __half g_Ehi[MAXN * MAXD];
__device__ float    g_sq[MAXN];
__device__ float    g_hp2[MAXN];
__device__ float    g_hpB2[MAXN];
__device__ unsigned g_hnfb[MAXN];
__device__ unsigned g_hnsemi[MAXN];
__device__ int      g_semiflag;
__device__ int      g_ccount[NB];
__device__ int      g_coff[NB];
__device__ int      g_clist[MAXN];

__device__ __forceinline__ uint32_t smem_u32(const void* p) {
    uint32_t a;
    asm("{ .reg .u64 t; cvta.to.shared.u64 t, %1; cvt.u32.u64 %0, t; }" : "=r"(a) : "l"(p));
    return a;
}

#define CP_ASYNC16(dst, src) \
    asm volatile("cp.async.cg.shared.global [%0], [%1], 16;" :: "r"(dst), "l"(src))
#define CP_COMMIT() asm volatile("cp.async.commit_group;")
#define CP_WAIT2()  asm volatile("cp.async.wait_group 2;")
#define CP_WAIT1()  asm volatile("cp.async.wait_group 1;")
#define CP_WAIT0()  asm volatile("cp.async.wait_group 0;")

#define LDM4(r0, r1, r2, r3, addr)                                              \
    asm volatile("ldmatrix.sync.aligned.m8n8.x4.shared.b16 {%0,%1,%2,%3}, [%4];" \
        : "=r"(r0), "=r"(r1), "=r"(r2), "=r"(r3) : "r"(addr))

#define MMA16816(c, a, b0, b1)                                                   \
    asm volatile("mma.sync.aligned.m16n8k16.row.col.f32.f16.f16.f32 "            \
        "{%0,%1,%2,%3},{%4,%5,%6,%7},{%8,%9},{%0,%1,%2,%3};"                     \
        : "+f"((c)[0]), "+f"((c)[1]), "+f"((c)[2]), "+f"((c)[3])                 \
        : "r"((a)[0]), "r"((a)[1]), "r"((a)[2]), "r"((a)[3]), "r"(b0), "r"(b1))

// ---------------- kernel 0: convert(hi only) + row sq + per-row init ----------------
__global__ void convsq_kernel(const float* __restrict__ E, int d) {
    int row = blockIdx.x;
    int t = threadIdx.x;
    const float4* p = (const float4*)(E + (size_t)row * d);
    int d4 = d >> 2;
    float s = 0.f;
    for (int c = t; c < d4; c += blockDim.x) {
        float4 v = p[c];
        s += v.x * v.x + v.y * v.y + v.z * v.z + v.w * v.w;
        __half2 h01 = __halves2half2(__float2half(v.x), __float2half(v.y));
        __half2 h23 = __halves2half2(__float2half(v.z), __float2half(v.w));
        size_t o = (size_t)row * d + 4 * c;
        *(__half2*)(g_Ehi + o) = h01;
        *(__half2*)(g_Ehi + o + 2) = h23;
    }
    for (int o = 16; o; o >>= 1) s += __shfl_xor_sync(0xffffffffu, s, o);
    __shared__ float ws[4];
    int lane = t & 31, w = t >> 5;
    if (lane == 0) ws[w] = s;
    __syncthreads();
    if (t == 0) {
        float tot = 0.f;
        for (int k = 0; k < (int)(blockDim.x >> 5); k++) tot += ws[k];
        g_sq[row] = tot;
        g_hnfb[row] = 0u;
        g_hnsemi[row] = __float_as_uint(BIGD2);
        if (row == 0) g_semiflag = 0;
    }
}

// ---------------- kernel 1: hist + scan + fill (single block) ----------------
__global__ void classlist_kernel(const int* __restrict__ labels, int n) {
    __shared__ int cnt[NB];
    __shared__ int s[NB];
    __shared__ int cur[NB];
    int t = threadIdx.x;
    cnt[t] = 0;
    __syncthreads();
    for (int i = t; i < n; i += blockDim.x) atomicAdd(&cnt[labels[i] & (NB - 1)], 1);
    __syncthreads();
    int v = cnt[t];
    s[t] = v;
    for (int off = 1; off < NB; off <<= 1) {
        __syncthreads();
        int u = (t >= off) ? s[t - off] : 0;
        __syncthreads();
        s[t] += u;
    }
    __syncthreads();
    int excl = s[t] - v;
    g_coff[t] = excl;
    g_ccount[t] = v;
    cur[t] = excl;
    __syncthreads();
    for (int i = t; i < n; i += blockDim.x) {
        int c = labels[i] & (NB - 1);
        int pos = atomicAdd(&cur[c], 1);
        g_clist[pos] = i;
    }
}

// ---------------- kernel 2: exact fp32 hardest positive (block per anchor, 4 warps) --
__global__ void hp_kernel(const float* __restrict__ E, const int* __restrict__ labels,
                          int n, int d) {
    int anchor = blockIdx.x;
    int lid = threadIdx.x & 31, wid = threadIdx.x >> 5;
    int c = labels[anchor] & (NB - 1);
    const float4* ea = (const float4*)(E + (size_t)anchor * d);
    int dk4 = d >> 7;                       // 4 for d=512
    float4 a0[MAXD / 128];
#pragma unroll
    for (int j = 0; j < MAXD / 128; j++) if (j < dk4) a0[j] = ea[lid + 32 * j];
    int beg = g_coff[c], cnt = g_ccount[c];
    float sqa = g_sq[anchor];
    float maxd2 = 0.f;
    for (int t = wid; t < cnt; t += 4) {
        int m = g_clist[beg + t];
        const float4* em = (const float4*)(E + (size_t)m * d);
        float dot = 0.f;
#pragma unroll
        for (int j = 0; j < MAXD / 128; j++)
            if (j < dk4) {
                float4 b = em[lid + 32 * j];
                dot += a0[j].x * b.x + a0[j].y * b.y + a0[j].z * b.z + a0[j].w * b.w;
            }
        for (int o = 16; o; o >>= 1) dot += __shfl_xor_sync(0xffffffffu, dot, o);
        float d2 = sqa + g_sq[m] - 2.f * dot;
        maxd2 = fmaxf(maxd2, d2);
    }
    __shared__ float wmax[4];
    if (lid == 0) wmax[wid] = maxd2;
    __syncthreads();
    if (threadIdx.x == 0) {
        float h2 = fmaxf(fmaxf(fmaxf(wmax[0], wmax[1]), fmaxf(wmax[2], wmax[3])), 1e-12f);
        g_hp2[anchor] = h2;
        float hp = sqrtf(h2);
        g_hpB2[anchor] = (hp + MARGIN) * (hp + MARGIN);
    }
}

// ------- kernel 3: HMMA GEMM, BK=64 (128B rows), 4-stage pipeline, 8 chunks ---------
#define BK      64                    // halves per k-chunk = 128 bytes
#define TILEB   16384                 // 128 rows * 128 B
#define STAGEB  (2 * TILEB)           // Ahi, Bhi = 32 KB
#define NSTAGE  4
#define AUXO    (NSTAGE * STAGEB)     // 131072
#define SMEM_DYN (AUXO + 6144)

__device__ __forceinline__ uint32_t swz(int r, int ch) {   // 128B-row xor swizzle
    return (uint32_t)(r * 128 + ((ch ^ (r & 7)) << 4));
}

__global__ __launch_bounds__(512, 1) void gemm_kernel(const int* __restrict__ labels,
                                                      int n, int d) {
    extern __shared__ char sm[];
    uint32_t sb = smem_u32(sm);
    int tid = threadIdx.x, lane = tid & 31, wid = tid >> 5;
    int wm = wid >> 2, wn = wid & 3;   // 4x4 warp grid; warp tile 32x32

    // triangle mapping: bid -> (by, bx), bx <= by
    int bid = blockIdx.x;
    int by = (int)((sqrtf(8.f * (float)bid + 1.f) - 1.f) * 0.5f);
    while ((by + 1) * (by + 2) / 2 <= bid) by++;
    while (by * (by + 1) / 2 > bid) by--;
    int bx = bid - by * (by + 1) / 2;
    int rowBase = by * 128, colBase = bx * 128;
    bool diag = (bx == by);

    float*    s_sqc  = (float*)(sm + AUXO);
    int*      s_labc = (int*)(sm + AUXO + 512);
    float*    s_sqr  = (float*)(sm + AUXO + 1024);
    int*      s_labr = (int*)(sm + AUXO + 1536);
    float*    s_hp2r = (float*)(sm + AUXO + 2048);
    float*    s_hpBr = (float*)(sm + AUXO + 2560);
    float*    s_hp2c = (float*)(sm + AUXO + 3072);
    float*    s_hpBc = (float*)(sm + AUXO + 3584);
    unsigned* shRmax = (unsigned*)(sm + AUXO + 4096);
    unsigned* shRmin = (unsigned*)(sm + AUXO + 4608);
    unsigned* shCmax = (unsigned*)(sm + AUXO + 5120);
    unsigned* shCmin = (unsigned*)(sm + AUXO + 5632);

    if (tid < 128) {
        s_sqc[tid]  = g_sq[colBase + tid];  s_labc[tid] = labels[colBase + tid];
        s_sqr[tid]  = g_sq[rowBase + tid];  s_labr[tid] = labels[rowBase + tid];
        s_hp2r[tid] = g_hp2[rowBase + tid]; s_hpBr[tid] = g_hpB2[rowBase + tid];
        s_hp2c[tid] = g_hp2[colBase + tid]; s_hpBc[tid] = g_hpB2[colBase + tid];
        shRmax[tid] = 0u; shRmin[tid] = __float_as_uint(BIGD2);
        shCmax[tid] = 0u; shCmin[tid] = __float_as_uint(BIGD2);
    }

    // cp.async: per stage 2 tiles x 1024 chunks(16B) / 512 threads = 4 per thread
    const __half* gsrc[4];
    uint32_t sdst[4];
    {
        const __half* tps[2] = {g_Ehi + (size_t)rowBase * d,
                                g_Ehi + (size_t)colBase * d};
#pragma unroll
        for (int j = 0; j < 4; j++) {
            int t = j >> 1;                    // tile
            int w = ((j & 1) << 9) + tid;      // 0..1023
            int r = w >> 3, ch = w & 7;
            gsrc[j] = tps[t] + (size_t)r * d + ch * 8;
            sdst[j] = sb + t * TILEB + swz(r, ch);
        }
    }

    // per-lane ldmatrix addresses for 4 k16-steps (chunk = 2*step + colsel)
    int r0A = wm * 32 + (lane & 15);
    int cA  = lane >> 4;
    int r0B = wn * 32 + (lane & 7) + ((lane >> 4) & 1) * 8;
    int cB  = (lane >> 3) & 1;
    uint32_t aoff[4], boff[4];
#pragma unroll
    for (int s = 0; s < 4; s++) {
        aoff[s] = swz(r0A, 2 * s + cA);
        boff[s] = swz(r0B, 2 * s + cB);
    }

    float acc[2][4][4];
#pragma unroll
    for (int im = 0; im < 2; im++)
#pragma unroll
        for (int in = 0; in < 4; in++)
#pragma unroll
            for (int e = 0; e < 4; e++) acc[im][in][e] = 0.f;

    int NC = d / BK;   // 8

    // prologue: stages 0,1,2
#pragma unroll
    for (int st = 0; st < 3; st++) {
#pragma unroll
        for (int j = 0; j < 4; j++) CP_ASYNC16(sdst[j] + st * STAGEB, gsrc[j] + st * BK);
        CP_COMMIT();
    }

    int cb = 0, ib = 3;
    for (int c = 0; c < NC; c++) {
        if (c + 3 <= NC)      { CP_WAIT2(); }
        else if (c + 2 <= NC) { CP_WAIT1(); }
        else                  { CP_WAIT0(); }
        __syncthreads();                       // stage cb visible; stage ib free
        if (c + 3 < NC) {
            int k0 = (c + 3) * BK;
            uint32_t so = (uint32_t)ib * STAGEB;
#pragma unroll
            for (int j = 0; j < 4; j++) CP_ASYNC16(sdst[j] + so, gsrc[j] + k0);
            CP_COMMIT();
            ib = (ib + 1) & 3;
        }

        uint32_t base = sb + (uint32_t)cb * STAGEB;
#pragma unroll
        for (int h = 0; h < 2; h++) {          // two half-chunks of 2 k16-steps
            uint32_t ah[2][2][4], bh[2][4][2];
#pragma unroll
            for (int s2 = 0; s2 < 2; s2++) {
                int s = 2 * h + s2;
#pragma unroll
                for (int im = 0; im < 2; im++) {
                    uint32_t aA = base + im * 2048 + aoff[s];
                    LDM4(ah[s2][im][0], ah[s2][im][1], ah[s2][im][2], ah[s2][im][3], aA);
                }
#pragma unroll
                for (int p = 0; p < 2; p++) {
                    uint32_t aB = base + TILEB + p * 2048 + boff[s];
                    LDM4(bh[s2][2 * p][0], bh[s2][2 * p][1],
                         bh[s2][2 * p + 1][0], bh[s2][2 * p + 1][1], aB);
                }
            }
#pragma unroll
            for (int s2 = 0; s2 < 2; s2++)
#pragma unroll
                for (int im = 0; im < 2; im++)
#pragma unroll
                    for (int in = 0; in < 4; in++)
                        MMA16816(acc[im][in], ah[s2][im], bh[s2][in][0], bh[s2][in][1]);
        }
        cb = (cb + 1) & 3;
    }

    // ---- epilogue: row-side ----
#pragma unroll
    for (int im = 0; im < 2; im++)
#pragma unroll
        for (int eh = 0; eh < 2; eh++) {
            int rloc = wm * 32 + im * 16 + (lane >> 2) + eh * 8;
            float sqr = s_sqr[rloc];
            int   labr = s_labr[rloc];
            float A = s_hp2r[rloc], B = s_hpBr[rloc];
            float mx = 0.f, mn = BIGD2;
#pragma unroll
            for (int in = 0; in < 4; in++)
#pragma unroll
                for (int ec = 0; ec < 2; ec++) {
                    int cloc = wn * 32 + in * 8 + (lane & 3) * 2 + ec;
                    float dot = acc[im][in][eh * 2 + ec];
                    float d2 = fmaxf(sqr + s_sqc[cloc] - 2.f * dot, 1e-12f);
                    if (labr != s_labc[cloc]) {
                        mx = fmaxf(mx, d2);
                        if (d2 > A && d2 < B) mn = fminf(mn, d2);
                    }
                }
            if (mx > 0.f) atomicMax(&shRmax[rloc], __float_as_uint(mx));
            if (mn < BIGD2) atomicMin(&shRmin[rloc], __float_as_uint(mn));
        }

    // ---- epilogue: col-side (skip on diagonal tiles: identical to row-side) ----
    if (!diag) {
#pragma unroll
        for (int in = 0; in < 4; in++)
#pragma unroll
            for (int ec = 0; ec < 2; ec++) {
                int cloc = wn * 32 + in * 8 + (lane & 3) * 2 + ec;
                float sqc = s_sqc[cloc];
                int   labc = s_labc[cloc];
                float A = s_hp2c[cloc], B = s_hpBc[cloc];
                float mx = 0.f, mn = BIGD2;
#pragma unroll
                for (int im = 0; im < 2; im++)
#pragma unroll
                    for (int eh = 0; eh < 2; eh++) {
                        int rloc = wm * 32 + im * 16 + (lane >> 2) + eh * 8;
                        float dot = acc[im][in][eh * 2 + ec];
                        float d2 = fmaxf(s_sqr[rloc] + sqc - 2.f * dot, 1e-12f);
                        if (labc != s_labr[rloc]) {
                            mx = fmaxf(mx, d2);
                            if (d2 > A && d2 < B) mn = fminf(mn, d2);
                        }
                    }
                if (mx > 0.f) atomicMax(&shCmax[cloc], __float_as_uint(mx));
                if (mn < BIGD2) atomicMin(&shCmin[cloc], __float_as_uint(mn));
            }
    }

    __syncthreads();
    if (tid < 128) {
        if (shRmax[tid]) atomicMax(&g_hnfb[rowBase + tid], shRmax[tid]);
        if (shRmin[tid] != __float_as_uint(BIGD2)) {
            atomicMin(&g_hnsemi[rowBase + tid], shRmin[tid]);
            g_semiflag = 1;
        }
        if (!diag) {
            if (shCmax[tid]) atomicMax(&g_hnfb[colBase + tid], shCmax[tid]);
            if (shCmin[tid] != __float_as_uint(BIGD2)) {
                atomicMin(&g_hnsemi[colBase + tid], shCmin[tid]);
                g_semiflag = 1;
            }
        }
    }
}

// ---------------- kernel 4: finalize ----------------
__global__ void finalize_kernel(float* __restrict__ out, int n) {
    bool useSemi = (g_semiflag != 0);
    float sum = 0.f;
    int cnt = 0;
    for (int i = threadIdx.x; i < n; i += blockDim.x) {
        float hp = sqrtf(g_hp2[i]);
        unsigned hb = useSemi ? g_hnsemi[i] : g_hnfb[i];
        float hn = sqrtf(__uint_as_float(hb));
        float t = hp - hn + MARGIN;
        if (t < 0.f) t = 0.f;
        sum += t;
        if (t > 0.f) cnt++;
    }
    for (int o = 16; o; o >>= 1) {
        sum += __shfl_xor_sync(0xffffffffu, sum, o);
        cnt += __shfl_xor_sync(0xffffffffu, cnt, o);
    }
    __shared__ float wsum[32];
    __shared__ int wcnt[32];
    int lane = threadIdx.x & 31, w = threadIdx.x >> 5;
    if (lane == 0) { wsum[w] = sum; wcnt[w] = cnt; }
    __syncthreads();
    if (threadIdx.x == 0) {
        float s = 0.f; int c = 0;
        for (int k = 0; k < (int)(blockDim.x >> 5); k++) { s += wsum[k]; c += wcnt[k]; }
        out[0] = (c > 0) ? (s / (float)c) : 0.0f;
    }
}

// ---------------- launch ----------------
extern "C" void kernel_launch(void* const* d_in, const int* in_sizes, int n_in,
                              void* d_out, int out_size) {
    const float* E = (const float*)d_in[0];
    const int* labels = (const int*)d_in[1];
    int n = in_sizes[1];
    int d = in_sizes[0] / n;

    cudaFuncSetAttribute(gemm_kernel, cudaFuncAttributeMaxDynamicSharedMemorySize, SMEM_DYN);

    convsq_kernel<<<n, 128>>>(E, d);                       // launch 0
    classlist_kernel<<<1, NB>>>(labels, n);                // launch 1
    hp_kernel<<<n, 128>>>(E, labels, n, d);                // launch 2
    int nb = n / 128;
    gemm_kernel<<<nb * (nb + 1) / 2, 512, SMEM_DYN>>>(labels, n, d);  // launch 3 (profiled)
    finalize_kernel<<<1, 1024>>>((float*)d_out, n);        // launch 4
}